// round 2
// baseline (speedup 1.0000x reference)
#include <cuda_runtime.h>
#include <stdint.h>

// Embedding gather: out[t, :] = weight[token_ids[t], :]
// token_ids: int32 [4*2048 = 8192]
// weight:    fp32  [32000, 1024]
// out:       fp32  [8192, 1024]
//
// One CTA per token row. 256 threads x float4 = 4096 B = one full row.
// Pure HBM-bound copy; perfectly coalesced loads and stores.

#define DIM 1024
#define VEC (DIM / 4)   // 256 float4 per row

__global__ __launch_bounds__(256, 8)
void embedding_gather_kernel(const int* __restrict__ token_ids,
                             const float4* __restrict__ weight,
                             float4* __restrict__ out,
                             int n_tokens)
{
    int row = blockIdx.x;
    if (row >= n_tokens) return;

    int tok = __ldg(&token_ids[row]);
    const float4* src = weight + (size_t)tok * VEC;
    float4* dst = out + (size_t)row * VEC;

    int t = threadIdx.x;  // 0..255, exactly VEC threads
    dst[t] = __ldg(&src[t]);
}

extern "C" void kernel_launch(void* const* d_in, const int* in_sizes, int n_in,
                              void* d_out, int out_size)
{
    // Identify inputs by size: token_ids is the small int32 array,
    // weight is the large fp32 matrix (VOCAB * DIM elements).
    const int* token_ids = (const int*)d_in[0];
    const float4* weight = (const float4*)d_in[1];
    int n_tokens = in_sizes[0];

    if (n_in >= 2 && in_sizes[0] > in_sizes[1]) {
        // order swapped: d_in[0] is the weight matrix
        token_ids = (const int*)d_in[1];
        weight = (const float4*)d_in[0];
        n_tokens = in_sizes[1];
    }

    // Cross-check against output size (out is n_tokens * DIM floats).
    int n_from_out = out_size / DIM;
    if (n_from_out > 0 && n_from_out != n_tokens) n_tokens = n_from_out;

    float4* out = (float4*)d_out;
    embedding_gather_kernel<<<n_tokens, 256>>>(token_ids, weight, out, n_tokens);
}

// round 3
// speedup vs baseline: 1.0186x; 1.0186x over previous
#include <cuda_runtime.h>
#include <stdint.h>

// Embedding gather: out[t, :] = weight[token_ids[t], :]
// token_ids: int32 [4*2048 = 8192]
// weight:    fp32  [32000, 1024]
// out:       fp32  [8192, 1024]
//
// One CTA per token row. 256 threads x float4 = 4096 B = one full row.
// Pure HBM-bound copy; perfectly coalesced loads and stores.

#define DIM 1024
#define VEC (DIM / 4)   // 256 float4 per row

__global__ __launch_bounds__(256, 8)
void embedding_gather_kernel(const int* __restrict__ token_ids,
                             const float4* __restrict__ weight,
                             float4* __restrict__ out,
                             int n_tokens)
{
    int row = blockIdx.x;
    if (row >= n_tokens) return;

    int tok = __ldg(&token_ids[row]);
    const float4* src = weight + (size_t)tok * VEC;
    float4* dst = out + (size_t)row * VEC;

    int t = threadIdx.x;  // 0..255, exactly VEC threads
    dst[t] = __ldg(&src[t]);
}

extern "C" void kernel_launch(void* const* d_in, const int* in_sizes, int n_in,
                              void* d_out, int out_size)
{
    // Identify inputs by size: token_ids is the small int32 array,
    // weight is the large fp32 matrix (VOCAB * DIM elements).
    const int* token_ids = (const int*)d_in[0];
    const float4* weight = (const float4*)d_in[1];
    int n_tokens = in_sizes[0];

    if (n_in >= 2 && in_sizes[0] > in_sizes[1]) {
        // order swapped: d_in[0] is the weight matrix
        token_ids = (const int*)d_in[1];
        weight = (const float4*)d_in[0];
        n_tokens = in_sizes[1];
    }

    // Cross-check against output size (out is n_tokens * DIM floats).
    int n_from_out = out_size / DIM;
    if (n_from_out > 0 && n_from_out != n_tokens) n_tokens = n_from_out;

    float4* out = (float4*)d_out;
    embedding_gather_kernel<<<n_tokens, 256>>>(token_ids, weight, out, n_tokens);
}